// round 1
// baseline (speedup 1.0000x reference)
#include <cuda_runtime.h>
#include <cuda_bf16.h>

#define H 8
#define FIN 128
#define HID 128
#define FOUT 64
#define LDA 136          // padded smem stride (elements): bank = 4*row + tig -> conflict-free frags
#define NMAX 131072
#define NTMAX (NMAX / 128)
#define NCH 16

// Scratch (static device globals; no runtime allocation)
__device__ float g_h[(size_t)NMAX * H * HID];         // intermediate h [N,H,HID]
__device__ float g_psum[(size_t)H * NTMAX * HID];     // per-tile column sums
__device__ float g_psumsq[(size_t)H * NTMAX * HID];
__device__ float g_ps2[H * NCH * HID];
__device__ float g_pq2[H * NCH * HID];
__device__ float g_scale[H * HID];
__device__ float g_shift[H * HID];

__device__ __forceinline__ void bsplit(float f, __nv_bfloat16 &hi, __nv_bfloat16 &lo) {
    hi = __float2bfloat16(f);
    lo = __float2bfloat16(f - __bfloat162float(hi));
}

__device__ __forceinline__ unsigned lds32(const __nv_bfloat16 *p) {
    return *reinterpret_cast<const unsigned *>(p);
}

__device__ __forceinline__ void st_bf2(__nv_bfloat16 *p, __nv_bfloat16 a, __nv_bfloat16 b) {
    __nv_bfloat162 t; t.x = a; t.y = b;
    *reinterpret_cast<__nv_bfloat162 *>(p) = t;
}

__device__ __forceinline__ void mma16816(float c[4], const unsigned a[4], const unsigned b[2]) {
    asm volatile(
        "mma.sync.aligned.m16n8k16.row.col.f32.bf16.bf16.f32 "
        "{%0,%1,%2,%3}, {%4,%5,%6,%7}, {%8,%9}, {%0,%1,%2,%3};\n"
        : "+f"(c[0]), "+f"(c[1]), "+f"(c[2]), "+f"(c[3])
        : "r"(a[0]), "r"(a[1]), "r"(a[2]), "r"(a[3]), "r"(b[0]), "r"(b[1]));
}

// ---------------------------------------------------------------------------
// K1: h = x @ w1 + b1 (per head), bf16-split MMA, fp32 accum.
// Writes h to g_h and per-tile column sum/sumsq to g_psum/g_psumsq.
// Block: 256 threads, tile = 128 rows x 128 cols, one head.
// ---------------------------------------------------------------------------
__global__ void __launch_bounds__(256, 1)
k_gemm1(const float *__restrict__ x, const float *__restrict__ w1,
        const float *__restrict__ b1, int N, int NT)
{
    extern __shared__ unsigned char smraw[];
    __nv_bfloat16 *Ahi = (__nv_bfloat16 *)smraw;
    __nv_bfloat16 *Alo = Ahi + 128 * LDA;
    __nv_bfloat16 *Bhi = Alo + 128 * LDA;
    __nv_bfloat16 *Blo = Bhi + 128 * LDA;
    float *psS = (float *)(Blo + 128 * LDA);   // [4][HID]
    float *pqS = psS + 4 * HID;                // [4][HID]

    const int tid = threadIdx.x;
    const int hd = blockIdx.y;
    const int n0 = blockIdx.x * 128;

    // ---- fill A (x tile), split into hi/lo bf16 ----
    #pragma unroll
    for (int i = tid; i < 128 * 32; i += 256) {
        int r = i >> 5, c4 = (i & 31) << 2;
        float4 v = make_float4(0.f, 0.f, 0.f, 0.f);
        int row = n0 + r;
        if (row < N)
            v = *reinterpret_cast<const float4 *>(x + ((size_t)row * H + hd) * FIN + c4);
        __nv_bfloat16 h0, h1, h2, h3, l0, l1, l2, l3;
        bsplit(v.x, h0, l0); bsplit(v.y, h1, l1);
        bsplit(v.z, h2, l2); bsplit(v.w, h3, l3);
        st_bf2(Ahi + r * LDA + c4, h0, h1); st_bf2(Ahi + r * LDA + c4 + 2, h2, h3);
        st_bf2(Alo + r * LDA + c4, l0, l1); st_bf2(Alo + r * LDA + c4 + 2, l2, l3);
    }

    // ---- fill B = w1^T into smem [n][k] (n-fast mapping: coalesced loads, conflict-free stores)
    const float *w1h = w1 + (size_t)hd * FIN * HID;
    #pragma unroll
    for (int i = tid; i < 128 * 32; i += 256) {
        int n = i & 127, kq = i >> 7;
        int k = kq * 4;
        float v0 = w1h[(size_t)(k + 0) * HID + n];
        float v1 = w1h[(size_t)(k + 1) * HID + n];
        float v2 = w1h[(size_t)(k + 2) * HID + n];
        float v3 = w1h[(size_t)(k + 3) * HID + n];
        __nv_bfloat16 h0, h1, h2, h3, l0, l1, l2, l3;
        bsplit(v0, h0, l0); bsplit(v1, h1, l1);
        bsplit(v2, h2, l2); bsplit(v3, h3, l3);
        st_bf2(Bhi + n * LDA + k, h0, h1); st_bf2(Bhi + n * LDA + k + 2, h2, h3);
        st_bf2(Blo + n * LDA + k, l0, l1); st_bf2(Blo + n * LDA + k + 2, l2, l3);
    }
    __syncthreads();

    const int lane = tid & 31;
    const int w = tid >> 5;
    const int gid = lane >> 2, tig = lane & 3;
    const int wm = w & 3, wn = w >> 2;     // warp tile: rows wm*32.., cols wn*64..

    float acc[2][8][4];
    #pragma unroll
    for (int mf = 0; mf < 2; mf++)
        #pragma unroll
        for (int nf = 0; nf < 8; nf++)
            #pragma unroll
            for (int q = 0; q < 4; q++) acc[mf][nf][q] = 0.f;

    const int ar0 = wm * 32 + gid;
    const int bn0 = wn * 64 + gid;

    #pragma unroll
    for (int kc = 0; kc < 8; kc++) {
        const int k0 = kc * 16 + tig * 2;
        unsigned ah[2][4], al[2][4];
        #pragma unroll
        for (int mf = 0; mf < 2; mf++) {
            const __nv_bfloat16 *p = Ahi + (ar0 + mf * 16) * LDA + k0;
            ah[mf][0] = lds32(p);            ah[mf][1] = lds32(p + 8 * LDA);
            ah[mf][2] = lds32(p + 8);        ah[mf][3] = lds32(p + 8 * LDA + 8);
            const __nv_bfloat16 *q = Alo + (ar0 + mf * 16) * LDA + k0;
            al[mf][0] = lds32(q);            al[mf][1] = lds32(q + 8 * LDA);
            al[mf][2] = lds32(q + 8);        al[mf][3] = lds32(q + 8 * LDA + 8);
        }
        unsigned bh[8][2], bl[8][2];
        #pragma unroll
        for (int nf = 0; nf < 8; nf++) {
            const __nv_bfloat16 *p = Bhi + (bn0 + nf * 8) * LDA + k0;
            bh[nf][0] = lds32(p);            bh[nf][1] = lds32(p + 8);
            const __nv_bfloat16 *q = Blo + (bn0 + nf * 8) * LDA + k0;
            bl[nf][0] = lds32(q);            bl[nf][1] = lds32(q + 8);
        }
        #pragma unroll
        for (int mf = 0; mf < 2; mf++)
            #pragma unroll
            for (int nf = 0; nf < 8; nf++) {
                mma16816(acc[mf][nf], ah[mf], bh[nf]);   // hi*hi
                mma16816(acc[mf][nf], ah[mf], bl[nf]);   // hi*lo
                mma16816(acc[mf][nf], al[mf], bh[nf]);   // lo*hi
            }
    }

    // ---- epilogue: +b1, store h, per-column stats ----
    const float *b1h = b1 + hd * HID;
    #pragma unroll
    for (int nf = 0; nf < 8; nf++) {
        const int col = wn * 64 + nf * 8 + tig * 2;
        const float be = b1h[col], bo = b1h[col + 1];
        float se = 0.f, qe = 0.f, so = 0.f, qo = 0.f;
        #pragma unroll
        for (int mf = 0; mf < 2; mf++) {
            const int r0 = n0 + wm * 32 + mf * 16 + gid;
            const int r1 = r0 + 8;
            float v0 = acc[mf][nf][0] + be;
            float v1 = acc[mf][nf][1] + bo;
            float v2 = acc[mf][nf][2] + be;
            float v3 = acc[mf][nf][3] + bo;
            if (r0 < N) {
                float2 t; t.x = v0; t.y = v1;
                *reinterpret_cast<float2 *>(g_h + ((size_t)r0 * H + hd) * HID + col) = t;
                se += v0; qe += v0 * v0; so += v1; qo += v1 * v1;
            }
            if (r1 < N) {
                float2 t; t.x = v2; t.y = v3;
                *reinterpret_cast<float2 *>(g_h + ((size_t)r1 * H + hd) * HID + col) = t;
                se += v2; qe += v2 * v2; so += v3; qo += v3 * v3;
            }
        }
        #pragma unroll
        for (int off = 16; off >= 4; off >>= 1) {
            se += __shfl_xor_sync(0xffffffffu, se, off);
            so += __shfl_xor_sync(0xffffffffu, so, off);
            qe += __shfl_xor_sync(0xffffffffu, qe, off);
            qo += __shfl_xor_sync(0xffffffffu, qo, off);
        }
        if (gid == 0) {
            psS[wm * HID + col] = se; psS[wm * HID + col + 1] = so;
            pqS[wm * HID + col] = qe; pqS[wm * HID + col + 1] = qo;
        }
    }
    __syncthreads();
    if (tid < HID) {
        float s = psS[tid] + psS[HID + tid] + psS[2 * HID + tid] + psS[3 * HID + tid];
        float q = pqS[tid] + pqS[HID + tid] + pqS[2 * HID + tid] + pqS[3 * HID + tid];
        size_t o = ((size_t)hd * NT + blockIdx.x) * HID + tid;
        g_psum[o] = s; g_psumsq[o] = q;
    }
}

// ---------------------------------------------------------------------------
// K2a/K2b: deterministic fixed-order reduction of tile stats -> BN scale/shift
// ---------------------------------------------------------------------------
__global__ void k_stats_a(int NT)
{
    const int hd = blockIdx.x, ch = blockIdx.y, c = threadIdx.x;
    const int per = (NT + NCH - 1) / NCH;
    int t0 = ch * per;
    int t1 = min(NT, t0 + per);
    const float *ps = g_psum + (size_t)hd * NT * HID + c;
    const float *pq = g_psumsq + (size_t)hd * NT * HID + c;
    float s0 = 0, s1 = 0, s2 = 0, s3 = 0, q0 = 0, q1 = 0, q2 = 0, q3 = 0;
    int t = t0;
    for (; t + 4 <= t1; t += 4) {
        s0 += ps[(size_t)(t + 0) * HID]; q0 += pq[(size_t)(t + 0) * HID];
        s1 += ps[(size_t)(t + 1) * HID]; q1 += pq[(size_t)(t + 1) * HID];
        s2 += ps[(size_t)(t + 2) * HID]; q2 += pq[(size_t)(t + 2) * HID];
        s3 += ps[(size_t)(t + 3) * HID]; q3 += pq[(size_t)(t + 3) * HID];
    }
    for (; t < t1; t++) { s0 += ps[(size_t)t * HID]; q0 += pq[(size_t)t * HID]; }
    g_ps2[(hd * NCH + ch) * HID + c] = (s0 + s1) + (s2 + s3);
    g_pq2[(hd * NCH + ch) * HID + c] = (q0 + q1) + (q2 + q3);
}

__global__ void k_stats_b(const float *__restrict__ bn_w, const float *__restrict__ bn_b, int N)
{
    const int hd = blockIdx.x, c = threadIdx.x;
    float s = 0.f, q = 0.f;
    #pragma unroll
    for (int ch = 0; ch < NCH; ch++) {
        s += g_ps2[(hd * NCH + ch) * HID + c];
        q += g_pq2[(hd * NCH + ch) * HID + c];
    }
    float invN = 1.0f / (float)N;
    float mean = s * invN;
    float var = fmaxf(q * invN - mean * mean, 0.f);
    float inv = rsqrtf(var + 1e-5f);
    float sc = bn_w[hd * HID + c] * inv;
    g_scale[hd * HID + c] = sc;
    g_shift[hd * HID + c] = bn_b[hd * HID + c] - mean * sc;
}

// ---------------------------------------------------------------------------
// K3: y = relu(h*scale + shift) @ w2 + b2, bf16-split MMA.
// Block: 256 threads, tile = 128 rows x 64 cols, one head.
// ---------------------------------------------------------------------------
__global__ void __launch_bounds__(256, 1)
k_gemm2(const float *__restrict__ w2, const float *__restrict__ b2,
        float *__restrict__ out, int N)
{
    extern __shared__ unsigned char smraw[];
    __nv_bfloat16 *Ahi = (__nv_bfloat16 *)smraw;
    __nv_bfloat16 *Alo = Ahi + 128 * LDA;
    __nv_bfloat16 *Bhi = Alo + 128 * LDA;
    __nv_bfloat16 *Blo = Bhi + 64 * LDA;
    float *scS = (float *)(Blo + 64 * LDA);
    float *shS = scS + HID;

    const int tid = threadIdx.x;
    const int hd = blockIdx.y;
    const int n0 = blockIdx.x * 128;

    if (tid < HID) {
        scS[tid] = g_scale[hd * HID + tid];
        shS[tid] = g_shift[hd * HID + tid];
    }
    __syncthreads();

    // ---- fill A = relu(h*s + t), split hi/lo ----
    #pragma unroll
    for (int i = tid; i < 128 * 32; i += 256) {
        int r = i >> 5, c4 = (i & 31) << 2;
        int row = n0 + r;
        float4 v = make_float4(0.f, 0.f, 0.f, 0.f);
        if (row < N)
            v = *reinterpret_cast<const float4 *>(g_h + ((size_t)row * H + hd) * HID + c4);
        float a0 = fmaxf(v.x * scS[c4 + 0] + shS[c4 + 0], 0.f);
        float a1 = fmaxf(v.y * scS[c4 + 1] + shS[c4 + 1], 0.f);
        float a2 = fmaxf(v.z * scS[c4 + 2] + shS[c4 + 2], 0.f);
        float a3 = fmaxf(v.w * scS[c4 + 3] + shS[c4 + 3], 0.f);
        if (row >= N) { a0 = a1 = a2 = a3 = 0.f; }
        __nv_bfloat16 h0, h1, h2, h3, l0, l1, l2, l3;
        bsplit(a0, h0, l0); bsplit(a1, h1, l1);
        bsplit(a2, h2, l2); bsplit(a3, h3, l3);
        st_bf2(Ahi + r * LDA + c4, h0, h1); st_bf2(Ahi + r * LDA + c4 + 2, h2, h3);
        st_bf2(Alo + r * LDA + c4, l0, l1); st_bf2(Alo + r * LDA + c4 + 2, l2, l3);
    }

    // ---- fill B = w2^T [n][k] ----
    const float *w2h = w2 + (size_t)hd * HID * FOUT;
    #pragma unroll
    for (int i = tid; i < 64 * 32; i += 256) {
        int n = i & 63, kq = i >> 6;
        int k = kq * 4;
        float v0 = w2h[(size_t)(k + 0) * FOUT + n];
        float v1 = w2h[(size_t)(k + 1) * FOUT + n];
        float v2 = w2h[(size_t)(k + 2) * FOUT + n];
        float v3 = w2h[(size_t)(k + 3) * FOUT + n];
        __nv_bfloat16 h0, h1, h2, h3, l0, l1, l2, l3;
        bsplit(v0, h0, l0); bsplit(v1, h1, l1);
        bsplit(v2, h2, l2); bsplit(v3, h3, l3);
        st_bf2(Bhi + n * LDA + k, h0, h1); st_bf2(Bhi + n * LDA + k + 2, h2, h3);
        st_bf2(Blo + n * LDA + k, l0, l1); st_bf2(Blo + n * LDA + k + 2, l2, l3);
    }
    __syncthreads();

    const int lane = tid & 31;
    const int w = tid >> 5;
    const int gid = lane >> 2, tig = lane & 3;
    const int wm = w & 3, wn = w >> 2;     // warp tile: rows wm*32.., cols wn*32..

    float acc[2][4][4];
    #pragma unroll
    for (int mf = 0; mf < 2; mf++)
        #pragma unroll
        for (int nf = 0; nf < 4; nf++)
            #pragma unroll
            for (int q = 0; q < 4; q++) acc[mf][nf][q] = 0.f;

    const int ar0 = wm * 32 + gid;
    const int bn0 = wn * 32 + gid;

    #pragma unroll
    for (int kc = 0; kc < 8; kc++) {
        const int k0 = kc * 16 + tig * 2;
        unsigned ah[2][4], al[2][4];
        #pragma unroll
        for (int mf = 0; mf < 2; mf++) {
            const __nv_bfloat16 *p = Ahi + (ar0 + mf * 16) * LDA + k0;
            ah[mf][0] = lds32(p);            ah[mf][1] = lds32(p + 8 * LDA);
            ah[mf][2] = lds32(p + 8);        ah[mf][3] = lds32(p + 8 * LDA + 8);
            const __nv_bfloat16 *q = Alo + (ar0 + mf * 16) * LDA + k0;
            al[mf][0] = lds32(q);            al[mf][1] = lds32(q + 8 * LDA);
            al[mf][2] = lds32(q + 8);        al[mf][3] = lds32(q + 8 * LDA + 8);
        }
        unsigned bh[4][2], bl[4][2];
        #pragma unroll
        for (int nf = 0; nf < 4; nf++) {
            const __nv_bfloat16 *p = Bhi + (bn0 + nf * 8) * LDA + k0;
            bh[nf][0] = lds32(p);            bh[nf][1] = lds32(p + 8);
            const __nv_bfloat16 *q = Blo + (bn0 + nf * 8) * LDA + k0;
            bl[nf][0] = lds32(q);            bl[nf][1] = lds32(q + 8);
        }
        #pragma unroll
        for (int mf = 0; mf < 2; mf++)
            #pragma unroll
            for (int nf = 0; nf < 4; nf++) {
                mma16816(acc[mf][nf], ah[mf], bh[nf]);
                mma16816(acc[mf][nf], ah[mf], bl[nf]);
                mma16816(acc[mf][nf], al[mf], bh[nf]);
            }
    }

    // ---- epilogue: +b2, store y ----
    const float *b2h = b2 + hd * FOUT;
    #pragma unroll
    for (int nf = 0; nf < 4; nf++) {
        const int col = wn * 32 + nf * 8 + tig * 2;
        const float be = b2h[col], bo = b2h[col + 1];
        #pragma unroll
        for (int mf = 0; mf < 2; mf++) {
            const int r0 = n0 + wm * 32 + mf * 16 + gid;
            const int r1 = r0 + 8;
            if (r0 < N) {
                float2 t; t.x = acc[mf][nf][0] + be; t.y = acc[mf][nf][1] + bo;
                *reinterpret_cast<float2 *>(out + ((size_t)r0 * H + hd) * FOUT + col) = t;
            }
            if (r1 < N) {
                float2 t; t.x = acc[mf][nf][2] + be; t.y = acc[mf][nf][3] + bo;
                *reinterpret_cast<float2 *>(out + ((size_t)r1 * H + hd) * FOUT + col) = t;
            }
        }
    }
}

// ---------------------------------------------------------------------------
extern "C" void kernel_launch(void *const *d_in, const int *in_sizes, int n_in,
                              void *d_out, int out_size)
{
    (void)n_in; (void)out_size;
    const float *x    = (const float *)d_in[0];
    const float *w1   = (const float *)d_in[1];
    const float *b1   = (const float *)d_in[2];
    const float *bn_w = (const float *)d_in[3];
    const float *bn_b = (const float *)d_in[4];
    const float *w2   = (const float *)d_in[5];
    const float *b2   = (const float *)d_in[6];
    float *out = (float *)d_out;

    const int N = in_sizes[0] / (H * FIN);
    const int NT = (N + 127) / 128;

    const int SM1 = 4 * 128 * LDA * 2 + 2 * 4 * HID * 4;               // 143360 B
    const int SM3 = (2 * 128 * LDA + 2 * 64 * LDA) * 2 + 2 * HID * 4;  // 105472 B

    cudaFuncSetAttribute(k_gemm1, cudaFuncAttributeMaxDynamicSharedMemorySize, SM1);
    cudaFuncSetAttribute(k_gemm2, cudaFuncAttributeMaxDynamicSharedMemorySize, SM3);

    k_gemm1<<<dim3(NT, H), 256, SM1>>>(x, w1, b1, N, NT);
    k_stats_a<<<dim3(H, NCH), HID>>>(NT);
    k_stats_b<<<H, HID>>>(bn_w, bn_b, N);
    k_gemm2<<<dim3(NT, H), 256, SM3>>>(w2, b2, out, N);
}

// round 2
// speedup vs baseline: 1.1162x; 1.1162x over previous
#include <cuda_runtime.h>
#include <cuda_bf16.h>

#define H 8
#define FIN 128
#define HID 128
#define FOUT 64
#define LDA 136          // padded smem stride (elems): 272B rows -> ldmatrix conflict-free
#define NMAX 131072
#define NTMAX (NMAX / 128)
#define NCH 16

// Scratch (static device globals; no runtime allocation)
__device__ float g_h[(size_t)NMAX * H * HID];         // intermediate h [N,H,HID]
__device__ float g_psum[(size_t)H * NTMAX * HID];     // per-tile column sums
__device__ float g_psumsq[(size_t)H * NTMAX * HID];
__device__ float g_ps2[H * NCH * HID];
__device__ float g_pq2[H * NCH * HID];
__device__ float g_scale[H * HID];
__device__ float g_shift[H * HID];

__device__ __forceinline__ void bsplit(float f, __nv_bfloat16 &hi, __nv_bfloat16 &lo) {
    hi = __float2bfloat16(f);
    lo = __float2bfloat16(f - __bfloat162float(hi));
}

__device__ __forceinline__ void st_bf2(__nv_bfloat16 *p, __nv_bfloat16 a, __nv_bfloat16 b) {
    __nv_bfloat162 t; t.x = a; t.y = b;
    *reinterpret_cast<__nv_bfloat162 *>(p) = t;
}

__device__ __forceinline__ void ldsm4(unsigned &r0, unsigned &r1, unsigned &r2, unsigned &r3,
                                      unsigned addr) {
    asm volatile("ldmatrix.sync.aligned.m8n8.x4.shared.b16 {%0,%1,%2,%3}, [%4];\n"
                 : "=r"(r0), "=r"(r1), "=r"(r2), "=r"(r3) : "r"(addr));
}

__device__ __forceinline__ void mma16816(float c[4], const unsigned a[4],
                                         unsigned b0, unsigned b1) {
    asm volatile(
        "mma.sync.aligned.m16n8k16.row.col.f32.bf16.bf16.f32 "
        "{%0,%1,%2,%3}, {%4,%5,%6,%7}, {%8,%9}, {%0,%1,%2,%3};\n"
        : "+f"(c[0]), "+f"(c[1]), "+f"(c[2]), "+f"(c[3])
        : "r"(a[0]), "r"(a[1]), "r"(a[2]), "r"(a[3]), "r"(b0), "r"(b1));
}

// ---------------------------------------------------------------------------
// K1: h = x @ w1 + b1 (per head), 3-pass bf16-split MMA, fp32 accum.
// 512 threads, block tile 128x128, warp grid 4x4 (warp tile 32x32).
// Writes h and per-tile column sum/sumsq.
// ---------------------------------------------------------------------------
__global__ void __launch_bounds__(512, 1)
k_gemm1(const float *__restrict__ x, const float *__restrict__ w1,
        const float *__restrict__ b1, int N, int NT)
{
    extern __shared__ unsigned char smraw[];
    __nv_bfloat16 *Ahi = (__nv_bfloat16 *)smraw;
    __nv_bfloat16 *Alo = Ahi + 128 * LDA;
    __nv_bfloat16 *Bhi = Alo + 128 * LDA;
    __nv_bfloat16 *Blo = Bhi + 128 * LDA;
    float *psS = (float *)(Blo + 128 * LDA);   // [4][HID]
    float *pqS = psS + 4 * HID;                // [4][HID]

    const int tid = threadIdx.x;
    const int hd = blockIdx.y;
    const int n0 = blockIdx.x * 128;

    // ---- fill A (x tile), split into hi/lo bf16 ----
    #pragma unroll
    for (int i = tid; i < 128 * 32; i += 512) {
        int r = i >> 5, c4 = (i & 31) << 2;
        float4 v = make_float4(0.f, 0.f, 0.f, 0.f);
        int row = n0 + r;
        if (row < N)
            v = *reinterpret_cast<const float4 *>(x + ((size_t)row * H + hd) * FIN + c4);
        __nv_bfloat16 h0, h1, h2, h3, l0, l1, l2, l3;
        bsplit(v.x, h0, l0); bsplit(v.y, h1, l1);
        bsplit(v.z, h2, l2); bsplit(v.w, h3, l3);
        st_bf2(Ahi + r * LDA + c4, h0, h1); st_bf2(Ahi + r * LDA + c4 + 2, h2, h3);
        st_bf2(Alo + r * LDA + c4, l0, l1); st_bf2(Alo + r * LDA + c4 + 2, l2, l3);
    }

    // ---- fill B = w1^T into smem [n][k] ----
    const float *w1h = w1 + (size_t)hd * FIN * HID;
    #pragma unroll
    for (int i = tid; i < 128 * 32; i += 512) {
        int n = i & 127, kq = i >> 7;
        int k = kq * 4;
        float v0 = w1h[(size_t)(k + 0) * HID + n];
        float v1 = w1h[(size_t)(k + 1) * HID + n];
        float v2 = w1h[(size_t)(k + 2) * HID + n];
        float v3 = w1h[(size_t)(k + 3) * HID + n];
        __nv_bfloat16 h0, h1, h2, h3, l0, l1, l2, l3;
        bsplit(v0, h0, l0); bsplit(v1, h1, l1);
        bsplit(v2, h2, l2); bsplit(v3, h3, l3);
        st_bf2(Bhi + n * LDA + k, h0, h1); st_bf2(Bhi + n * LDA + k + 2, h2, h3);
        st_bf2(Blo + n * LDA + k, l0, l1); st_bf2(Blo + n * LDA + k + 2, l2, l3);
    }
    __syncthreads();

    const int lane = tid & 31;
    const int w = tid >> 5;
    const int gid = lane >> 2, tig = lane & 3;
    const int wm = w & 3, wn = w >> 2;     // warp tile: rows wm*32.., cols wn*32..

    // ldmatrix per-lane addresses
    const int lr = lane & 15;                   // row within 16-row tile
    const int kh = ((lane >> 4) & 1) << 3;      // k-half offset (elems)
    unsigned sAhi = (unsigned)__cvta_generic_to_shared(Ahi);
    unsigned sAlo = (unsigned)__cvta_generic_to_shared(Alo);
    unsigned sBhi = (unsigned)__cvta_generic_to_shared(Bhi);
    unsigned sBlo = (unsigned)__cvta_generic_to_shared(Blo);
    unsigned aHiAd[2], aLoAd[2], bHiAd[2], bLoAd[2];
    #pragma unroll
    for (int mf = 0; mf < 2; mf++) {
        unsigned off = ((wm * 32 + mf * 16 + lr) * LDA + kh) * 2;
        aHiAd[mf] = sAhi + off; aLoAd[mf] = sAlo + off;
    }
    #pragma unroll
    for (int g = 0; g < 2; g++) {
        unsigned off = ((wn * 32 + g * 16 + lr) * LDA + kh) * 2;
        bHiAd[g] = sBhi + off; bLoAd[g] = sBlo + off;
    }

    float acc[2][4][4];
    #pragma unroll
    for (int mf = 0; mf < 2; mf++)
        #pragma unroll
        for (int nf = 0; nf < 4; nf++)
            #pragma unroll
            for (int q = 0; q < 4; q++) acc[mf][nf][q] = 0.f;

    #pragma unroll
    for (int kc = 0; kc < 8; kc++) {
        const unsigned kadv = kc * 32;          // 16 elems * 2B
        unsigned ah[2][4], al[2][4], bh[2][4], bl[2][4];
        #pragma unroll
        for (int mf = 0; mf < 2; mf++) {
            ldsm4(ah[mf][0], ah[mf][1], ah[mf][2], ah[mf][3], aHiAd[mf] + kadv);
            ldsm4(al[mf][0], al[mf][1], al[mf][2], al[mf][3], aLoAd[mf] + kadv);
        }
        #pragma unroll
        for (int g = 0; g < 2; g++) {
            ldsm4(bh[g][0], bh[g][1], bh[g][2], bh[g][3], bHiAd[g] + kadv);
            ldsm4(bl[g][0], bl[g][1], bl[g][2], bl[g][3], bLoAd[g] + kadv);
        }
        #pragma unroll
        for (int mf = 0; mf < 2; mf++)
            #pragma unroll
            for (int g = 0; g < 2; g++) {
                // sub-group 0: cols g*16 + 0..7 -> b-frag {r0, r2}
                mma16816(acc[mf][g * 2 + 0], ah[mf], bh[g][0], bh[g][2]);
                mma16816(acc[mf][g * 2 + 0], ah[mf], bl[g][0], bl[g][2]);
                mma16816(acc[mf][g * 2 + 0], al[mf], bh[g][0], bh[g][2]);
                // sub-group 1: cols g*16 + 8..15 -> b-frag {r1, r3}
                mma16816(acc[mf][g * 2 + 1], ah[mf], bh[g][1], bh[g][3]);
                mma16816(acc[mf][g * 2 + 1], ah[mf], bl[g][1], bl[g][3]);
                mma16816(acc[mf][g * 2 + 1], al[mf], bh[g][1], bh[g][3]);
            }
    }

    // ---- epilogue: +b1, store h, per-column stats ----
    const float *b1h = b1 + hd * HID;
    #pragma unroll
    for (int nf = 0; nf < 4; nf++) {
        const int col = wn * 32 + nf * 8 + tig * 2;
        const float be = b1h[col], bo = b1h[col + 1];
        float se = 0.f, qe = 0.f, so = 0.f, qo = 0.f;
        #pragma unroll
        for (int mf = 0; mf < 2; mf++) {
            const int r0 = n0 + wm * 32 + mf * 16 + gid;
            const int r1 = r0 + 8;
            float v0 = acc[mf][nf][0] + be;
            float v1 = acc[mf][nf][1] + bo;
            float v2 = acc[mf][nf][2] + be;
            float v3 = acc[mf][nf][3] + bo;
            if (r0 < N) {
                float2 t; t.x = v0; t.y = v1;
                *reinterpret_cast<float2 *>(g_h + ((size_t)r0 * H + hd) * HID + col) = t;
                se += v0; qe += v0 * v0; so += v1; qo += v1 * v1;
            }
            if (r1 < N) {
                float2 t; t.x = v2; t.y = v3;
                *reinterpret_cast<float2 *>(g_h + ((size_t)r1 * H + hd) * HID + col) = t;
                se += v2; qe += v2 * v2; so += v3; qo += v3 * v3;
            }
        }
        #pragma unroll
        for (int off = 16; off >= 4; off >>= 1) {
            se += __shfl_xor_sync(0xffffffffu, se, off);
            so += __shfl_xor_sync(0xffffffffu, so, off);
            qe += __shfl_xor_sync(0xffffffffu, qe, off);
            qo += __shfl_xor_sync(0xffffffffu, qo, off);
        }
        if (gid == 0) {
            // 4 n-warp-columns are disjoint; 4 m-warps stack in rows of psS
            psS[wm * HID + col] = se; psS[wm * HID + col + 1] = so;
            pqS[wm * HID + col] = qe; pqS[wm * HID + col + 1] = qo;
        }
    }
    __syncthreads();
    if (tid < HID) {
        float s = psS[tid] + psS[HID + tid] + psS[2 * HID + tid] + psS[3 * HID + tid];
        float q = pqS[tid] + pqS[HID + tid] + pqS[2 * HID + tid] + pqS[3 * HID + tid];
        size_t o = ((size_t)hd * NT + blockIdx.x) * HID + tid;
        g_psum[o] = s; g_psumsq[o] = q;
    }
}

// ---------------------------------------------------------------------------
// K2a/K2b: deterministic fixed-order reduction of tile stats -> BN scale/shift
// ---------------------------------------------------------------------------
__global__ void k_stats_a(int NT)
{
    const int hd = blockIdx.x, ch = blockIdx.y, c = threadIdx.x;
    const int per = (NT + NCH - 1) / NCH;
    int t0 = ch * per;
    int t1 = min(NT, t0 + per);
    const float *ps = g_psum + (size_t)hd * NT * HID + c;
    const float *pq = g_psumsq + (size_t)hd * NT * HID + c;
    float s0 = 0, s1 = 0, s2 = 0, s3 = 0, q0 = 0, q1 = 0, q2 = 0, q3 = 0;
    int t = t0;
    for (; t + 4 <= t1; t += 4) {
        s0 += ps[(size_t)(t + 0) * HID]; q0 += pq[(size_t)(t + 0) * HID];
        s1 += ps[(size_t)(t + 1) * HID]; q1 += pq[(size_t)(t + 1) * HID];
        s2 += ps[(size_t)(t + 2) * HID]; q2 += pq[(size_t)(t + 2) * HID];
        s3 += ps[(size_t)(t + 3) * HID]; q3 += pq[(size_t)(t + 3) * HID];
    }
    for (; t < t1; t++) { s0 += ps[(size_t)t * HID]; q0 += pq[(size_t)t * HID]; }
    g_ps2[(hd * NCH + ch) * HID + c] = (s0 + s1) + (s2 + s3);
    g_pq2[(hd * NCH + ch) * HID + c] = (q0 + q1) + (q2 + q3);
}

__global__ void k_stats_b(const float *__restrict__ bn_w, const float *__restrict__ bn_b, int N)
{
    const int hd = blockIdx.x, c = threadIdx.x;
    float s = 0.f, q = 0.f;
    #pragma unroll
    for (int ch = 0; ch < NCH; ch++) {
        s += g_ps2[(hd * NCH + ch) * HID + c];
        q += g_pq2[(hd * NCH + ch) * HID + c];
    }
    float invN = 1.0f / (float)N;
    float mean = s * invN;
    float var = fmaxf(q * invN - mean * mean, 0.f);
    float inv = rsqrtf(var + 1e-5f);
    float sc = bn_w[hd * HID + c] * inv;
    g_scale[hd * HID + c] = sc;
    g_shift[hd * HID + c] = bn_b[hd * HID + c] - mean * sc;
}

// ---------------------------------------------------------------------------
// K3: y = relu(h*scale + shift) @ w2 + b2, 3-pass bf16-split MMA.
// 512 threads, block tile 128x64, warp grid 4x4 (warp tile 32x16).
// ---------------------------------------------------------------------------
__global__ void __launch_bounds__(512, 2)
k_gemm2(const float *__restrict__ w2, const float *__restrict__ b2,
        float *__restrict__ out, int N)
{
    extern __shared__ unsigned char smraw[];
    __nv_bfloat16 *Ahi = (__nv_bfloat16 *)smraw;
    __nv_bfloat16 *Alo = Ahi + 128 * LDA;
    __nv_bfloat16 *Bhi = Alo + 128 * LDA;
    __nv_bfloat16 *Blo = Bhi + 64 * LDA;
    float *scS = (float *)(Blo + 64 * LDA);
    float *shS = scS + HID;

    const int tid = threadIdx.x;
    const int hd = blockIdx.y;
    const int n0 = blockIdx.x * 128;

    if (tid < HID) {
        scS[tid] = g_scale[hd * HID + tid];
        shS[tid] = g_shift[hd * HID + tid];
    }
    __syncthreads();

    // ---- fill A = relu(h*s + t), split hi/lo ----
    #pragma unroll
    for (int i = tid; i < 128 * 32; i += 512) {
        int r = i >> 5, c4 = (i & 31) << 2;
        int row = n0 + r;
        float4 v = make_float4(0.f, 0.f, 0.f, 0.f);
        if (row < N)
            v = *reinterpret_cast<const float4 *>(g_h + ((size_t)row * H + hd) * HID + c4);
        float a0 = fmaxf(v.x * scS[c4 + 0] + shS[c4 + 0], 0.f);
        float a1 = fmaxf(v.y * scS[c4 + 1] + shS[c4 + 1], 0.f);
        float a2 = fmaxf(v.z * scS[c4 + 2] + shS[c4 + 2], 0.f);
        float a3 = fmaxf(v.w * scS[c4 + 3] + shS[c4 + 3], 0.f);
        if (row >= N) { a0 = a1 = a2 = a3 = 0.f; }
        __nv_bfloat16 h0, h1, h2, h3, l0, l1, l2, l3;
        bsplit(a0, h0, l0); bsplit(a1, h1, l1);
        bsplit(a2, h2, l2); bsplit(a3, h3, l3);
        st_bf2(Ahi + r * LDA + c4, h0, h1); st_bf2(Ahi + r * LDA + c4 + 2, h2, h3);
        st_bf2(Alo + r * LDA + c4, l0, l1); st_bf2(Alo + r * LDA + c4 + 2, l2, l3);
    }

    // ---- fill B = w2^T [n][k] ----
    const float *w2h = w2 + (size_t)hd * HID * FOUT;
    #pragma unroll
    for (int i = tid; i < 64 * 32; i += 512) {
        int n = i & 63, kq = i >> 6;
        int k = kq * 4;
        float v0 = w2h[(size_t)(k + 0) * FOUT + n];
        float v1 = w2h[(size_t)(k + 1) * FOUT + n];
        float v2 = w2h[(size_t)(k + 2) * FOUT + n];
        float v3 = w2h[(size_t)(k + 3) * FOUT + n];
        __nv_bfloat16 h0, h1, h2, h3, l0, l1, l2, l3;
        bsplit(v0, h0, l0); bsplit(v1, h1, l1);
        bsplit(v2, h2, l2); bsplit(v3, h3, l3);
        st_bf2(Bhi + n * LDA + k, h0, h1); st_bf2(Bhi + n * LDA + k + 2, h2, h3);
        st_bf2(Blo + n * LDA + k, l0, l1); st_bf2(Blo + n * LDA + k + 2, l2, l3);
    }
    __syncthreads();

    const int lane = tid & 31;
    const int w = tid >> 5;
    const int gid = lane >> 2, tig = lane & 3;
    const int wm = w & 3, wn = w >> 2;     // warp tile: rows wm*32.., cols wn*16..

    const int lr = lane & 15;
    const int kh = ((lane >> 4) & 1) << 3;
    unsigned sAhi = (unsigned)__cvta_generic_to_shared(Ahi);
    unsigned sAlo = (unsigned)__cvta_generic_to_shared(Alo);
    unsigned sBhi = (unsigned)__cvta_generic_to_shared(Bhi);
    unsigned sBlo = (unsigned)__cvta_generic_to_shared(Blo);
    unsigned aHiAd[2], aLoAd[2], bHiAd, bLoAd;
    #pragma unroll
    for (int mf = 0; mf < 2; mf++) {
        unsigned off = ((wm * 32 + mf * 16 + lr) * LDA + kh) * 2;
        aHiAd[mf] = sAhi + off; aLoAd[mf] = sAlo + off;
    }
    {
        unsigned off = ((wn * 16 + lr) * LDA + kh) * 2;
        bHiAd = sBhi + off; bLoAd = sBlo + off;
    }

    float acc[2][2][4];
    #pragma unroll
    for (int mf = 0; mf < 2; mf++)
        #pragma unroll
        for (int nf = 0; nf < 2; nf++)
            #pragma unroll
            for (int q = 0; q < 4; q++) acc[mf][nf][q] = 0.f;

    #pragma unroll
    for (int kc = 0; kc < 8; kc++) {
        const unsigned kadv = kc * 32;
        unsigned ah[2][4], al[2][4], bh[4], bl[4];
        #pragma unroll
        for (int mf = 0; mf < 2; mf++) {
            ldsm4(ah[mf][0], ah[mf][1], ah[mf][2], ah[mf][3], aHiAd[mf] + kadv);
            ldsm4(al[mf][0], al[mf][1], al[mf][2], al[mf][3], aLoAd[mf] + kadv);
        }
        ldsm4(bh[0], bh[1], bh[2], bh[3], bHiAd + kadv);
        ldsm4(bl[0], bl[1], bl[2], bl[3], bLoAd + kadv);
        #pragma unroll
        for (int mf = 0; mf < 2; mf++) {
            mma16816(acc[mf][0], ah[mf], bh[0], bh[2]);
            mma16816(acc[mf][0], ah[mf], bl[0], bl[2]);
            mma16816(acc[mf][0], al[mf], bh[0], bh[2]);
            mma16816(acc[mf][1], ah[mf], bh[1], bh[3]);
            mma16816(acc[mf][1], ah[mf], bl[1], bl[3]);
            mma16816(acc[mf][1], al[mf], bh[1], bh[3]);
        }
    }

    // ---- epilogue: +b2, store y ----
    const float *b2h = b2 + hd * FOUT;
    #pragma unroll
    for (int nf = 0; nf < 2; nf++) {
        const int col = wn * 16 + nf * 8 + tig * 2;
        const float be = b2h[col], bo = b2h[col + 1];
        #pragma unroll
        for (int mf = 0; mf < 2; mf++) {
            const int r0 = n0 + wm * 32 + mf * 16 + gid;
            const int r1 = r0 + 8;
            if (r0 < N) {
                float2 t; t.x = acc[mf][nf][0] + be; t.y = acc[mf][nf][1] + bo;
                *reinterpret_cast<float2 *>(out + ((size_t)r0 * H + hd) * FOUT + col) = t;
            }
            if (r1 < N) {
                float2 t; t.x = acc[mf][nf][2] + be; t.y = acc[mf][nf][3] + bo;
                *reinterpret_cast<float2 *>(out + ((size_t)r1 * H + hd) * FOUT + col) = t;
            }
        }
    }
}

// ---------------------------------------------------------------------------
extern "C" void kernel_launch(void *const *d_in, const int *in_sizes, int n_in,
                              void *d_out, int out_size)
{
    (void)n_in; (void)out_size;
    const float *x    = (const float *)d_in[0];
    const float *w1   = (const float *)d_in[1];
    const float *b1   = (const float *)d_in[2];
    const float *bn_w = (const float *)d_in[3];
    const float *bn_b = (const float *)d_in[4];
    const float *w2   = (const float *)d_in[5];
    const float *b2   = (const float *)d_in[6];
    float *out = (float *)d_out;

    const int N = in_sizes[0] / (H * FIN);
    const int NT = (N + 127) / 128;

    const int SM1 = 4 * 128 * LDA * 2 + 2 * 4 * HID * 4;               // 143360 B
    const int SM3 = (2 * 128 * LDA + 2 * 64 * LDA) * 2 + 2 * HID * 4;  // 105472 B

    cudaFuncSetAttribute(k_gemm1, cudaFuncAttributeMaxDynamicSharedMemorySize, SM1);
    cudaFuncSetAttribute(k_gemm2, cudaFuncAttributeMaxDynamicSharedMemorySize, SM3);

    k_gemm1<<<dim3(NT, H), 512, SM1>>>(x, w1, b1, N, NT);
    k_stats_a<<<dim3(H, NCH), HID>>>(NT);
    k_stats_b<<<H, HID>>>(bn_w, bn_b, N);
    k_gemm2<<<dim3(NT, H), 512, SM3>>>(w2, b2, out, N);
}